// round 11
// baseline (speedup 1.0000x reference)
#include <cuda_runtime.h>
#include <math.h>

// Problem constants (fixed by setup_inputs): N=16, T=2048, D=2
#define TT 2048
#define NBMAX 16
#define LOG2PI_F 1.8378770664093453f
#define LN2F     0.6931471805599453f

// Scratch (device globals; no allocation allowed)
__device__ float4 g_pack[NBMAX * TT];   // (A_j, xs_j, ys_j, 0)
__device__ float  g_logP[NBMAX * TT];   // log( sum_{j<i} exp(t_j/sp) )

__device__ __forceinline__ float ex2f(float x) {
    float r;
    asm("ex2.approx.f32 %0, %1;" : "=f"(r) : "f"(x));
    return r;
}

// ---------------------------------------------------------------------------
// Kernel A: per batch, build packed per-j data and prefix logP.
// ---------------------------------------------------------------------------
__global__ void prep_kernel(const float* __restrict__ tim,
                            const float* __restrict__ loc,
                            const float* __restrict__ cd_p,
                            const float* __restrict__ sls_p) {
    const int n   = blockIdx.x;
    const int tid = threadIdx.x;           // 256 threads
    const float cd  = *cd_p;
    const float sls = *sls_p;
    const float sp  = log1pf(__expf(cd));          // softplus(coeff_decay)
    const float rc2 = 1.0f / (sp * LN2F);
    const float h2l = 0.5f * __expf(-2.0f * sls) / LN2F;

    __shared__ float sE[TT];
    __shared__ float wtot[8];
    __shared__ float wbase[8];

    for (int j = tid; j < TT; j += 256) {
        float tj = tim[n * TT + j];
        float xj = loc[(n * TT + j) * 2 + 0];
        float yj = loc[(n * TT + j) * 2 + 1];
        float c2 = tj * rc2;
        float A  = fmaf(-h2l, fmaf(xj, xj, yj * yj), c2);
        float xs = 2.0f * h2l * xj;
        float ys = 2.0f * h2l * yj;
        g_pack[n * TT + j] = make_float4(A, xs, ys, 0.0f);
        sE[j] = ex2f(c2);
    }
    __syncthreads();

    const int C = TT / 256;                // 8
    float part = 0.0f;
#pragma unroll
    for (int kk = 0; kk < C; kk++) part += sE[tid * C + kk];

    float inc = part;
    const int lane = tid & 31;
#pragma unroll
    for (int o = 1; o < 32; o <<= 1) {
        float v = __shfl_up_sync(0xffffffffu, inc, o);
        if (lane >= o) inc += v;
    }
    if (lane == 31) wtot[tid >> 5] = inc;
    __syncthreads();
    if (tid < 8) {
        float v = wtot[tid], s = v;
#pragma unroll
        for (int o = 1; o < 8; o <<= 1) {
            float u = __shfl_up_sync(0x000000ffu, s, o);
            if (tid >= o) s += u;
        }
        wbase[tid] = s - v;
    }
    __syncthreads();

    float run = wbase[tid >> 5] + (inc - part);
#pragma unroll
    for (int kk = 0; kk < C; kk++) {
        int j = tid * C + kk;
        g_logP[n * TT + j] = (j == 0) ? 0.0f : __logf(run);
        run += sE[j];
    }
}

// ---------------------------------------------------------------------------
// Kernel B: block = (batch n, slice k of 8). 8 tiles:
//   ts[m] = (m odd) ? 63 - 8*(m/2) - k : k + 8*(m/2)
// Dense j-streams concatenated (total 8064 j); warp w processes slice
// [1008w, 1008(w+1)) -> EVERY warp does exactly 1008 dense + 31 tail j.
// Equal-length warps keep both warps of each SMSP co-active to the end
// (no solo phase -> MUFU stays 2-way interleaved). All segment bounds are
// multiples of 8. Whole 32KB j-stream staged in smem once; one barrier
// before the cross-warp per-tile reduction.
// Grid = 16*8 = 128 blocks -> one wave, one block per SM.
// ---------------------------------------------------------------------------
__global__ void __launch_bounds__(256, 1)
main_kernel(const float* __restrict__ loc,
            const float* __restrict__ mu0_p,
            const float* __restrict__ ls0_p,
            const float* __restrict__ sls_p,
            float* __restrict__ out) {
    const int b    = blockIdx.x;
    const int n    = b >> 3;               // batch
    const int k    = b & 7;                // slice
    const int tid  = threadIdx.x;
    const int wid  = tid >> 5;
    const int lane = tid & 31;

    __shared__ float4 sj[TT];              // 32KB: whole batch j-stream
    __shared__ float  sacc[8][8][32];      // 8KB: [writer warp][tile slot][lane]

    const float sls = *sls_p;
    const float h2l = 0.5f * __expf(-2.0f * sls) / LN2F;

    const float2* __restrict__ locv = (const float2*)loc;
    const float4* __restrict__ pk   = &g_pack[n * TT];

    // Stage the full 2048-entry stream
#pragma unroll
    for (int t = 0; t < TT / 256; t++)
        sj[t * 256 + tid] = pk[t * 256 + tid];

    // Zero my sacc row while the staging loads land
#pragma unroll
    for (int m = 0; m < 8; m++) sacc[wid][m][lane] = 0.0f;
    __syncthreads();

    // Tile list and prefix sums (compile-time foldable pattern)
    int ts[8], P[9];
    P[0] = 0;
#pragma unroll
    for (int m = 0; m < 8; m++) {
        ts[m] = (m & 1) ? (63 - ((m >> 1) << 3) - k) : (k + ((m >> 1) << 3));
        P[m + 1] = P[m] + (ts[m] << 5);
    }

    // Dense work: slice [1008*wid, 1008*(wid+1)) of the concatenated stream
    int pos = wid * 1008;
    const int endp = pos + 1008;
#pragma unroll
    for (int m = 0; m < 8; m++) {
        if (P[m + 1] > pos && pos < endp) {
            const int hi  = (endp < P[m + 1]) ? endp : P[m + 1];
            const int t   = ts[m];
            const float2 xy = locv[n * TT + (t << 5) + lane];
            const float xi = xy.x, yi = xy.y;

            float s0 = 0.0f, s1 = 0.0f, s2 = 0.0f, s3 = 0.0f;
            for (int j = pos - P[m]; j < hi - P[m]; j += 8) {   // mult of 8
                float4 p0 = sj[j + 0]; float4 p1 = sj[j + 1];
                float4 p2 = sj[j + 2]; float4 p3 = sj[j + 3];
                float4 p4 = sj[j + 4]; float4 p5 = sj[j + 5];
                float4 p6 = sj[j + 6]; float4 p7 = sj[j + 7];
                s0 += ex2f(fmaf(xi, p0.y, fmaf(yi, p0.z, p0.x)));
                s1 += ex2f(fmaf(xi, p1.y, fmaf(yi, p1.z, p1.x)));
                s2 += ex2f(fmaf(xi, p2.y, fmaf(yi, p2.z, p2.x)));
                s3 += ex2f(fmaf(xi, p3.y, fmaf(yi, p3.z, p3.x)));
                s0 += ex2f(fmaf(xi, p4.y, fmaf(yi, p4.z, p4.x)));
                s1 += ex2f(fmaf(xi, p5.y, fmaf(yi, p5.z, p5.x)));
                s2 += ex2f(fmaf(xi, p6.y, fmaf(yi, p6.z, p6.x)));
                s3 += ex2f(fmaf(xi, p7.y, fmaf(yi, p7.z, p7.x)));
            }
            sacc[wid][m][lane] = (s0 + s1) + (s2 + s3);
            pos = hi;
        }
    }

    // Triangular tail of tile ts[wid]: j = 32*t + jt, active for jt < lane
    {
        const int t    = ts[wid];
        const int base = t << 5;
        const float2 xy = locv[n * TT + base + lane];
        const float xi = xy.x, yi = xy.y;
        float st = 0.0f;
#pragma unroll
        for (int jt = 0; jt < 31; jt++) {
            float4 q = sj[base + jt];
            float e = ex2f(fmaf(xi, q.y, fmaf(yi, q.z, q.x)));
            st += (jt < lane) ? e : 0.0f;
        }
        sacc[wid][wid][lane] += st;
    }

    __syncthreads();                       // the only post-staging barrier

    // Reduction + epilogue: warp w owns tile ts[w]
    {
        const int t = ts[wid];
        const int i = (t << 5) + lane;
        float S = 0.0f;
#pragma unroll
        for (int w2 = 0; w2 < 8; w2++) S += sacc[w2][wid][lane];

        const float2 xy = locv[n * TT + i];
        const float xi = xy.x, yi = xy.y;

        float res;
        if (i == 0) {
            const float mu0 = *mu0_p;
            const float ls0 = *ls0_p;
            const float iv  = __expf(-2.0f * ls0);
            const float dx = xi - mu0, dy = yi - mu0;
            res = -0.5f * iv * fmaf(dx, dx, dy * dy) - 2.0f * ls0 - LOG2PI_F;
        } else {
            const float B2 = -h2l * fmaf(xi, xi, yi * yi);
            const float K  = 2.0f * sls + LOG2PI_F;
            res = __logf(S) + LN2F * B2 - K - g_logP[n * TT + i];
        }
        out[n * TT + i] = res;
    }
}

// ---------------------------------------------------------------------------
extern "C" void kernel_launch(void* const* d_in, const int* in_sizes, int n_in,
                              void* d_out, int out_size) {
    const float* tim  = (const float*)d_in[0];  // (N, T, 1)
    const float* loc  = (const float*)d_in[1];  // (N, T, 2)
    const float* mu0  = (const float*)d_in[2];
    const float* ls0  = (const float*)d_in[3];
    const float* cd   = (const float*)d_in[4];
    const float* sls  = (const float*)d_in[5];
    float* out = (float*)d_out;

    const int N = in_sizes[0] / TT;             // 16

    prep_kernel<<<N, 256>>>(tim, loc, cd, sls);
    main_kernel<<<N * 8, 256>>>(loc, mu0, ls0, sls, out);
}

// round 12
// speedup vs baseline: 2.5756x; 2.5756x over previous
#include <cuda_runtime.h>
#include <math.h>

// Problem constants (fixed by setup_inputs): N=16, T=2048, D=2
#define TT 2048
#define NBMAX 16
#define LOG2PI_F 1.8378770664093453f
#define LN2F     0.6931471805599453f

// Scratch (device globals; no allocation allowed)
__device__ float4 g_pack[NBMAX * TT];   // (A_j, xs_j, ys_j, 0)
__device__ float  g_logP[NBMAX * TT];   // log( sum_{j<i} exp(t_j/sp) )

__device__ __forceinline__ float ex2f(float x) {
    float r;
    asm("ex2.approx.f32 %0, %1;" : "=f"(r) : "f"(x));
    return r;
}

// ---------------------------------------------------------------------------
// Kernel A: per batch, build packed per-j data and prefix logP.
// ---------------------------------------------------------------------------
__global__ void prep_kernel(const float* __restrict__ tim,
                            const float* __restrict__ loc,
                            const float* __restrict__ cd_p,
                            const float* __restrict__ sls_p) {
    const int n   = blockIdx.x;
    const int tid = threadIdx.x;           // 256 threads
    const float cd  = *cd_p;
    const float sls = *sls_p;
    const float sp  = log1pf(__expf(cd));          // softplus(coeff_decay)
    const float rc2 = 1.0f / (sp * LN2F);
    const float h2l = 0.5f * __expf(-2.0f * sls) / LN2F;

    __shared__ float sE[TT];
    __shared__ float wtot[8];
    __shared__ float wbase[8];

    for (int j = tid; j < TT; j += 256) {
        float tj = tim[n * TT + j];
        float xj = loc[(n * TT + j) * 2 + 0];
        float yj = loc[(n * TT + j) * 2 + 1];
        float c2 = tj * rc2;
        float A  = fmaf(-h2l, fmaf(xj, xj, yj * yj), c2);
        float xs = 2.0f * h2l * xj;
        float ys = 2.0f * h2l * yj;
        g_pack[n * TT + j] = make_float4(A, xs, ys, 0.0f);
        sE[j] = ex2f(c2);
    }
    __syncthreads();

    const int C = TT / 256;                // 8
    float part = 0.0f;
#pragma unroll
    for (int kk = 0; kk < C; kk++) part += sE[tid * C + kk];

    float inc = part;
    const int lane = tid & 31;
#pragma unroll
    for (int o = 1; o < 32; o <<= 1) {
        float v = __shfl_up_sync(0xffffffffu, inc, o);
        if (lane >= o) inc += v;
    }
    if (lane == 31) wtot[tid >> 5] = inc;
    __syncthreads();
    if (tid < 8) {
        float v = wtot[tid], s = v;
#pragma unroll
        for (int o = 1; o < 8; o <<= 1) {
            float u = __shfl_up_sync(0x000000ffu, s, o);
            if (tid >= o) s += u;
        }
        wbase[tid] = s - v;
    }
    __syncthreads();

    float run = wbase[tid >> 5] + (inc - part);
#pragma unroll
    for (int kk = 0; kk < C; kk++) {
        int j = tid * C + kk;
        g_logP[n * TT + j] = (j == 0) ? 0.0f : __logf(run);
        run += sE[j];
    }
}

// ---------------------------------------------------------------------------
// Dense sum over sj[lo..hi) for row constants (xi, yi). hi-lo multiple of 8.
// Same unroll-8 body as the R7 kernel (proven to compile well).
// ---------------------------------------------------------------------------
__device__ __forceinline__ float dense_sum(const float4* __restrict__ sjv,
                                           int lo, int hi, float xi, float yi) {
    float s0 = 0.0f, s1 = 0.0f, s2 = 0.0f, s3 = 0.0f;
    for (int j = lo; j < hi; j += 8) {
        float4 p0 = sjv[j + 0]; float4 p1 = sjv[j + 1];
        float4 p2 = sjv[j + 2]; float4 p3 = sjv[j + 3];
        float4 p4 = sjv[j + 4]; float4 p5 = sjv[j + 5];
        float4 p6 = sjv[j + 6]; float4 p7 = sjv[j + 7];
        s0 += ex2f(fmaf(xi, p0.y, fmaf(yi, p0.z, p0.x)));
        s1 += ex2f(fmaf(xi, p1.y, fmaf(yi, p1.z, p1.x)));
        s2 += ex2f(fmaf(xi, p2.y, fmaf(yi, p2.z, p2.x)));
        s3 += ex2f(fmaf(xi, p3.y, fmaf(yi, p3.z, p3.x)));
        s0 += ex2f(fmaf(xi, p4.y, fmaf(yi, p4.z, p4.x)));
        s1 += ex2f(fmaf(xi, p5.y, fmaf(yi, p5.z, p5.x)));
        s2 += ex2f(fmaf(xi, p6.y, fmaf(yi, p6.z, p6.x)));
        s3 += ex2f(fmaf(xi, p7.y, fmaf(yi, p7.z, p7.x)));
    }
    return (s0 + s1) + (s2 + s3);
}

// ---------------------------------------------------------------------------
// Kernel B: block = (batch n, slice k of 8). 4 tile pairs, s = wid & 3:
//   tl = k + 8s (<=31),  th = 63 - tl (>=32),  rem = 1008 - 32*tl
// Warp s     (A): tile tl dense [0,32*tl) + tile th dense [0,rem) + tail(tl)
// Warp s+4   (B): tile th dense [rem, 32*th)                      + tail(th)
// Every warp: exactly 1008 dense + 31 tail j -> SMSP warp pairs stay
// co-active to the end (no solo phase). Whole 32KB j-stream staged once;
// one barrier; th's two partials combined via a 4x32 sacc.
// Grid = 16*8 = 128 blocks -> one wave, one block per SM.
// ---------------------------------------------------------------------------
__global__ void __launch_bounds__(256, 1)
main_kernel(const float* __restrict__ loc,
            const float* __restrict__ mu0_p,
            const float* __restrict__ ls0_p,
            const float* __restrict__ sls_p,
            float* __restrict__ out) {
    const int b    = blockIdx.x;
    const int n    = b >> 3;               // batch
    const int k    = b & 7;                // slice
    const int tid  = threadIdx.x;
    const int wid  = tid >> 5;
    const int lane = tid & 31;
    const int s    = wid & 3;
    const bool isA = (wid < 4);

    const int tl  = k + (s << 3);          // 0..31
    const int th  = 63 - tl;               // 32..63
    const int rem = 1008 - (tl << 5);      // >=16, multiple of 16

    __shared__ float4 sj[TT];              // 32KB: whole batch j-stream
    __shared__ float  sacc[4][32];         // A's partial of tile th

    const float sls = *sls_p;
    const float h2l = 0.5f * __expf(-2.0f * sls) / LN2F;

    const float2* __restrict__ locv = (const float2*)loc;
    const float4* __restrict__ pk   = &g_pack[n * TT];

    // Stage the full 2048-entry stream (8 independent LDG.128 per thread)
#pragma unroll
    for (int t = 0; t < TT / 256; t++)
        sj[t * 256 + tid] = pk[t * 256 + tid];
    __syncthreads();

    // Row constants: A owns rows of tl for its first loop + tail; both roles
    // need th's rows for the th work.
    const float2 xyl = locv[n * TT + (tl << 5) + lane];
    const float2 xyh = locv[n * TT + (th << 5) + lane];

    float sum_own = 0.0f;                  // A: tile tl total | B: tile th part
    float sum_thA = 0.0f;                  // A only: tile th partial

    if (isA) {
        sum_own = dense_sum(sj, 0, tl << 5, xyl.x, xyl.y);
        sum_thA = dense_sum(sj, 0, rem,     xyh.x, xyh.y);
        // tail of tile tl: j = 32*tl + jt, active for jt < lane
        const int base = tl << 5;
#pragma unroll
        for (int jt = 0; jt < 31; jt++) {
            float4 q = sj[base + jt];
            float e = ex2f(fmaf(xyl.x, q.y, fmaf(xyl.y, q.z, q.x)));
            sum_own += (jt < lane) ? e : 0.0f;
        }
        sacc[s][lane] = sum_thA;
    } else {
        sum_own = dense_sum(sj, rem, th << 5, xyh.x, xyh.y);
        // tail of tile th
        const int base = th << 5;
#pragma unroll
        for (int jt = 0; jt < 31; jt++) {
            float4 q = sj[base + jt];
            float e = ex2f(fmaf(xyh.x, q.y, fmaf(xyh.y, q.z, q.x)));
            sum_own += (jt < lane) ? e : 0.0f;
        }
    }
    __syncthreads();

    // Output: warp A writes tile tl, warp B writes tile th (adding A's part)
    const int   t_out = isA ? tl : th;
    const float2 xyo  = isA ? xyl : xyh;
    const float S     = isA ? sum_own : (sum_own + sacc[s][lane]);
    const int   i     = (t_out << 5) + lane;

    float res;
    if (i == 0) {
        const float mu0 = *mu0_p;
        const float ls0 = *ls0_p;
        const float iv  = __expf(-2.0f * ls0);
        const float dx = xyo.x - mu0, dy = xyo.y - mu0;
        res = -0.5f * iv * fmaf(dx, dx, dy * dy) - 2.0f * ls0 - LOG2PI_F;
    } else {
        const float B2 = -h2l * fmaf(xyo.x, xyo.x, xyo.y * xyo.y);
        const float K  = 2.0f * sls + LOG2PI_F;
        res = __logf(S) + LN2F * B2 - K - g_logP[n * TT + i];
    }
    out[n * TT + i] = res;
}

// ---------------------------------------------------------------------------
extern "C" void kernel_launch(void* const* d_in, const int* in_sizes, int n_in,
                              void* d_out, int out_size) {
    const float* tim  = (const float*)d_in[0];  // (N, T, 1)
    const float* loc  = (const float*)d_in[1];  // (N, T, 2)
    const float* mu0  = (const float*)d_in[2];
    const float* ls0  = (const float*)d_in[3];
    const float* cd   = (const float*)d_in[4];
    const float* sls  = (const float*)d_in[5];
    float* out = (float*)d_out;

    const int N = in_sizes[0] / TT;             // 16

    prep_kernel<<<N, 256>>>(tim, loc, cd, sls);
    main_kernel<<<N * 8, 256>>>(loc, mu0, ls0, sls, out);
}

// round 13
// speedup vs baseline: 3.1951x; 1.2405x over previous
#include <cuda_runtime.h>
#include <math.h>

// Problem constants (fixed by setup_inputs): N=16, T=2048, D=2
#define TT 2048
#define LOG2PI_F 1.8378770664093453f
#define LN2F     0.6931471805599453f

__device__ __forceinline__ float ex2f(float x) {
    float r;
    asm("ex2.approx.f32 %0, %1;" : "=f"(r) : "f"(x));
    return r;
}

// ---------------------------------------------------------------------------
// Dense sum over sj[lo..hi) for row constants (xi, yi). hi-lo multiple of 8.
// ---------------------------------------------------------------------------
__device__ __forceinline__ float dense_sum(const float4* __restrict__ sjv,
                                           int lo, int hi, float xi, float yi) {
    float s0 = 0.0f, s1 = 0.0f, s2 = 0.0f, s3 = 0.0f;
    for (int j = lo; j < hi; j += 8) {
        float4 p0 = sjv[j + 0]; float4 p1 = sjv[j + 1];
        float4 p2 = sjv[j + 2]; float4 p3 = sjv[j + 3];
        float4 p4 = sjv[j + 4]; float4 p5 = sjv[j + 5];
        float4 p6 = sjv[j + 6]; float4 p7 = sjv[j + 7];
        s0 += ex2f(fmaf(xi, p0.y, fmaf(yi, p0.z, p0.x)));
        s1 += ex2f(fmaf(xi, p1.y, fmaf(yi, p1.z, p1.x)));
        s2 += ex2f(fmaf(xi, p2.y, fmaf(yi, p2.z, p2.x)));
        s3 += ex2f(fmaf(xi, p3.y, fmaf(yi, p3.z, p3.x)));
        s0 += ex2f(fmaf(xi, p4.y, fmaf(yi, p4.z, p4.x)));
        s1 += ex2f(fmaf(xi, p5.y, fmaf(yi, p5.z, p5.x)));
        s2 += ex2f(fmaf(xi, p6.y, fmaf(yi, p6.z, p6.x)));
        s3 += ex2f(fmaf(xi, p7.y, fmaf(yi, p7.z, p7.x)));
    }
    return (s0 + s1) + (s2 + s3);
}

// ---------------------------------------------------------------------------
// Fused kernel. Block = (batch n, slice k of 8), 512 threads (16 warps).
// Phase 1 (prologue): build sj[j] = (A_j, xs_j, ys_j) and sE[j] = 2^{c2_j}
//   directly from tim/loc; in-place exclusive prefix scan of sE (P_i).
// Phase 2 (dense): 4 tile pairs (tl = k+8s, th = 63-tl), pair j-stream
//   (2016 j) split into 4 equal 504-j chunks for warps {s, s+4, s+8, s+12}
//   -> SMSP s carries exactly 2016 j with 4-way warp interleave, every warp
//   identical length. Tails (31 predicated j) on warps 0..7 (2 per SMSP).
// Phase 3: per-tile reduction (4 partials) + epilogue.
// Grid = 16*8 = 128 blocks -> one wave, one block per SM.
// ---------------------------------------------------------------------------
__global__ void __launch_bounds__(512, 1)
fused_kernel(const float* __restrict__ tim,
             const float* __restrict__ loc,
             const float* __restrict__ mu0_p,
             const float* __restrict__ ls0_p,
             const float* __restrict__ cd_p,
             const float* __restrict__ sls_p,
             float* __restrict__ out) {
    const int b    = blockIdx.x;
    const int n    = b >> 3;               // batch
    const int k    = b & 7;                // slice
    const int tid  = threadIdx.x;
    const int wid  = tid >> 5;
    const int lane = tid & 31;
    const int s    = wid & 3;              // pair id == SMSP id
    const int c    = wid >> 2;             // chunk id 0..3

    __shared__ float4 sj[TT];              // 32KB: (A, xs, ys, -)
    __shared__ float  sE[TT];              // 8KB: E_j, then in-place prefix P_j
    __shared__ float  wtot[16], wbase[16];
    __shared__ float  saccl[16][32];       // per-warp partial for tile tl_s
    __shared__ float  sacch[16][32];       // per-warp partial for tile th_s

    const float cd  = *cd_p;
    const float sls = *sls_p;
    const float sp  = log1pf(__expf(cd));  // softplus(coeff_decay)
    const float rc2 = 1.0f / (sp * LN2F);
    const float h2l = 0.5f * __expf(-2.0f * sls) / LN2F;

    const float*  __restrict__ timn = tim + n * TT;
    const float2* __restrict__ locv = ((const float2*)loc) + n * TT;

    // ---- Phase 1a: build pack + E ----
#pragma unroll
    for (int t = 0; t < TT / 512; t++) {
        const int j = t * 512 + tid;
        const float  tj = timn[j];
        const float2 xy = locv[j];
        const float c2 = tj * rc2;
        const float A  = fmaf(-h2l, fmaf(xy.x, xy.x, xy.y * xy.y), c2);
        sj[j] = make_float4(A, 2.0f * h2l * xy.x, 2.0f * h2l * xy.y, 0.0f);
        sE[j] = ex2f(c2);
    }
    __syncthreads();

    // ---- Phase 1b: block scan (exclusive prefix of sE, in place) ----
    // Thread owns contiguous chunk [4*tid, 4*tid+4).
    {
        const int base = tid << 2;
        float e0 = sE[base + 0], e1 = sE[base + 1];
        float e2 = sE[base + 2], e3 = sE[base + 3];
        const float part = (e0 + e1) + (e2 + e3);

        float inc = part;
#pragma unroll
        for (int o = 1; o < 32; o <<= 1) {
            float v = __shfl_up_sync(0xffffffffu, inc, o);
            if (lane >= o) inc += v;
        }
        if (lane == 31) wtot[wid] = inc;
        __syncthreads();
        if (tid < 16) {
            float v = wtot[tid], s2 = v;
#pragma unroll
            for (int o = 1; o < 16; o <<= 1) {
                float u = __shfl_up_sync(0x0000ffffu, s2, o);
                if (tid >= o) s2 += u;
            }
            wbase[tid] = s2 - v;           // exclusive warp base
        }
        __syncthreads();

        float run = wbase[wid] + (inc - part);
        sE[base + 0] = run; run += e0;
        sE[base + 1] = run; run += e1;
        sE[base + 2] = run; run += e2;
        sE[base + 3] = run;                // (e3 unused beyond here)
    }
    __syncthreads();

    // ---- Phase 2: dense work ----
    const int tl  = k + (s << 3);          // 0..31
    const int th  = 63 - tl;               // 32..63
    const int bnd = tl << 5;               // tl's dense length in pair stream

    const float2 xyl = locv[(tl << 5) + lane];
    const float2 xyh = locv[(th << 5) + lane];

    const int lo = c * 504;
    const int hi = lo + 504;

    float suml = 0.0f, sumh = 0.0f;
    {
        const int e1 = (hi < bnd) ? hi : bnd;     // tl segment [lo, e1)
        if (lo < e1) suml = dense_sum(sj, lo, e1, xyl.x, xyl.y);
        const int a2 = (lo > bnd) ? lo : bnd;     // th segment [a2, hi)
        if (a2 < hi) sumh = dense_sum(sj, a2 - bnd, hi - bnd, xyh.x, xyh.y);
    }

    // Tails: warp s (wid<4) does tile tl's tail; warp s+4 (4<=wid<8) tile th's.
    if (wid < 4) {
        const int base = tl << 5;
#pragma unroll
        for (int jt = 0; jt < 31; jt++) {
            float4 q = sj[base + jt];
            float e = ex2f(fmaf(xyl.x, q.y, fmaf(xyl.y, q.z, q.x)));
            suml += (jt < lane) ? e : 0.0f;
        }
    } else if (wid < 8) {
        const int base = th << 5;
#pragma unroll
        for (int jt = 0; jt < 31; jt++) {
            float4 q = sj[base + jt];
            float e = ex2f(fmaf(xyh.x, q.y, fmaf(xyh.y, q.z, q.x)));
            sumh += (jt < lane) ? e : 0.0f;
        }
    }

    saccl[wid][lane] = suml;
    sacch[wid][lane] = sumh;
    __syncthreads();

    // ---- Phase 3: reduction + epilogue (warps 0..7) ----
    if (wid < 8) {
        const bool  low = (wid < 4);
        const int   ss  = wid & 3;
        const int   t_o = low ? (k + (ss << 3)) : (63 - (k + (ss << 3)));
        const int   i   = (t_o << 5) + lane;
        const float2 xyo = low ? locv[(t_o << 5) + lane]
                               : locv[(t_o << 5) + lane];

        float S = 0.0f;
#pragma unroll
        for (int m = 0; m < 4; m++)
            S += low ? saccl[ss + (m << 2)][lane] : sacch[ss + (m << 2)][lane];

        float res;
        if (i == 0) {
            const float mu0 = *mu0_p;
            const float ls0 = *ls0_p;
            const float iv  = __expf(-2.0f * ls0);
            const float dx = xyo.x - mu0, dy = xyo.y - mu0;
            res = -0.5f * iv * fmaf(dx, dx, dy * dy) - 2.0f * ls0 - LOG2PI_F;
        } else {
            const float B2 = -h2l * fmaf(xyo.x, xyo.x, xyo.y * xyo.y);
            const float K  = 2.0f * sls + LOG2PI_F;
            res = __logf(S) + LN2F * B2 - K - __logf(sE[i]);
        }
        out[n * TT + i] = res;
    }
}

// ---------------------------------------------------------------------------
extern "C" void kernel_launch(void* const* d_in, const int* in_sizes, int n_in,
                              void* d_out, int out_size) {
    const float* tim  = (const float*)d_in[0];  // (N, T, 1)
    const float* loc  = (const float*)d_in[1];  // (N, T, 2)
    const float* mu0  = (const float*)d_in[2];
    const float* ls0  = (const float*)d_in[3];
    const float* cd   = (const float*)d_in[4];
    const float* sls  = (const float*)d_in[5];
    float* out = (float*)d_out;

    const int N = in_sizes[0] / TT;             // 16

    fused_kernel<<<N * 8, 512>>>(tim, loc, mu0, ls0, cd, sls, out);
}

// round 14
// speedup vs baseline: 3.5817x; 1.1210x over previous
#include <cuda_runtime.h>
#include <math.h>

// Problem constants (fixed by setup_inputs): N=16, T=2048, D=2
#define TT 2048
#define LOG2PI_F 1.8378770664093453f
#define LN2F     0.6931471805599453f

__device__ __forceinline__ float ex2f(float x) {
    float r;
    asm("ex2.approx.f32 %0, %1;" : "=f"(r) : "f"(x));
    return r;
}

__device__ __forceinline__ unsigned long long pack2(float x) {
    unsigned long long d;
    asm("mov.b64 %0, {%1, %1};" : "=l"(d) : "f"(x));
    return d;
}

// u01 = xi2 * XS + (yi2 * YS + A)  in packed f32x2; unpack to (u0, u1).
__device__ __forceinline__ void pair_u(unsigned long long A,
                                       unsigned long long XS,
                                       unsigned long long YS,
                                       unsigned long long xi2,
                                       unsigned long long yi2,
                                       float& u0, float& u1) {
    asm("{\n\t"
        ".reg .b64 t;\n\t"
        "fma.rn.f32x2 t, %3, %4, %2;\n\t"
        "fma.rn.f32x2 t, %5, %6, t;\n\t"
        "mov.b64 {%0, %1}, t;\n\t"
        "}"
        : "=f"(u0), "=f"(u1)
        : "l"(A), "l"(yi2), "l"(YS), "l"(xi2), "l"(XS));
}

// ---------------------------------------------------------------------------
// Packed dense sum over j in [lo, hi) (multiples of 8) from SoA smem arrays.
// Per 8 j: 6 LDS.128 + 8 FFMA2 + 8 MUFU + 8 FADD.
// ---------------------------------------------------------------------------
__device__ __forceinline__ float dense_sum_p(const ulonglong2* __restrict__ A2,
                                             const ulonglong2* __restrict__ X2,
                                             const ulonglong2* __restrict__ Y2,
                                             int lo, int hi,
                                             unsigned long long xi2,
                                             unsigned long long yi2) {
    float s0 = 0.0f, s1 = 0.0f, s2 = 0.0f, s3 = 0.0f;
    for (int j = lo; j < hi; j += 8) {
        const int g = j >> 2;
        ulonglong2 a0 = A2[g], a1 = A2[g + 1];
        ulonglong2 x0 = X2[g], x1 = X2[g + 1];
        ulonglong2 y0 = Y2[g], y1 = Y2[g + 1];
        float u0, u1;
        pair_u(a0.x, x0.x, y0.x, xi2, yi2, u0, u1);
        s0 += ex2f(u0); s1 += ex2f(u1);
        pair_u(a0.y, x0.y, y0.y, xi2, yi2, u0, u1);
        s2 += ex2f(u0); s3 += ex2f(u1);
        pair_u(a1.x, x1.x, y1.x, xi2, yi2, u0, u1);
        s0 += ex2f(u0); s1 += ex2f(u1);
        pair_u(a1.y, x1.y, y1.y, xi2, yi2, u0, u1);
        s2 += ex2f(u0); s3 += ex2f(u1);
    }
    return (s0 + s1) + (s2 + s3);
}

// ---------------------------------------------------------------------------
// Fused kernel. Block = (batch n, slice k of 8), 512 threads (16 warps).
// Phase 1: build SoA sA/sxs/sys + sE = 2^{c2}; in-place exclusive scan of sE.
// Phase 2: 4 tile pairs (tl = k+8s, th = 63-tl), pair stream (2016 j) split
//   into 4 equal 504-j chunks for warps {s, s+4, s+8, s+12} (all SMSP s).
//   Tails (31 predicated j) on warps 0..7 (2 per SMSP).
// Phase 3: per-tile reduction + epilogue.
// Grid = 16*8 = 128 blocks -> one wave, one block per SM.
// ---------------------------------------------------------------------------
__global__ void __launch_bounds__(512, 1)
fused_kernel(const float* __restrict__ tim,
             const float* __restrict__ loc,
             const float* __restrict__ mu0_p,
             const float* __restrict__ ls0_p,
             const float* __restrict__ cd_p,
             const float* __restrict__ sls_p,
             float* __restrict__ out) {
    const int b    = blockIdx.x;
    const int n    = b >> 3;               // batch
    const int k    = b & 7;                // slice
    const int tid  = threadIdx.x;
    const int wid  = tid >> 5;
    const int lane = tid & 31;
    const int s    = wid & 3;              // pair id == SMSP id
    const int c    = wid >> 2;             // chunk id 0..3

    __shared__ __align__(16) float sA [TT];   // 8KB  A_j
    __shared__ __align__(16) float sxs[TT];   // 8KB  2*h2l*x_j
    __shared__ __align__(16) float sys[TT];   // 8KB  2*h2l*y_j
    __shared__ float  sE[TT];                 // 8KB  E_j -> prefix P_j
    __shared__ float  wtot[16], wbase[16];
    __shared__ float  saccl[16][32];
    __shared__ float  sacch[16][32];

    const float cd  = *cd_p;
    const float sls = *sls_p;
    const float sp  = log1pf(__expf(cd));  // softplus(coeff_decay)
    const float rc2 = 1.0f / (sp * LN2F);
    const float h2l = 0.5f * __expf(-2.0f * sls) / LN2F;

    const float*  __restrict__ timn = tim + n * TT;
    const float2* __restrict__ locv = ((const float2*)loc) + n * TT;

    // ---- Phase 1a: build SoA pack + E ----
#pragma unroll
    for (int t = 0; t < TT / 512; t++) {
        const int j = t * 512 + tid;
        const float  tj = timn[j];
        const float2 xy = locv[j];
        const float c2 = tj * rc2;
        sA [j] = fmaf(-h2l, fmaf(xy.x, xy.x, xy.y * xy.y), c2);
        sxs[j] = 2.0f * h2l * xy.x;
        sys[j] = 2.0f * h2l * xy.y;
        sE [j] = ex2f(c2);
    }
    __syncthreads();

    // ---- Phase 1b: block scan (exclusive prefix of sE, in place) ----
    {
        const int base = tid << 2;
        float e0 = sE[base + 0], e1 = sE[base + 1];
        float e2 = sE[base + 2], e3 = sE[base + 3];
        const float part = (e0 + e1) + (e2 + e3);

        float inc = part;
#pragma unroll
        for (int o = 1; o < 32; o <<= 1) {
            float v = __shfl_up_sync(0xffffffffu, inc, o);
            if (lane >= o) inc += v;
        }
        if (lane == 31) wtot[wid] = inc;
        __syncthreads();
        if (tid < 16) {
            float v = wtot[tid], s2 = v;
#pragma unroll
            for (int o = 1; o < 16; o <<= 1) {
                float u = __shfl_up_sync(0x0000ffffu, s2, o);
                if (tid >= o) s2 += u;
            }
            wbase[tid] = s2 - v;
        }
        __syncthreads();

        float run = wbase[wid] + (inc - part);
        sE[base + 0] = run; run += e0;
        sE[base + 1] = run; run += e1;
        sE[base + 2] = run; run += e2;
        sE[base + 3] = run;
    }
    __syncthreads();

    // ---- Phase 2: dense work (packed) ----
    const int tl  = k + (s << 3);          // 0..31
    const int th  = 63 - tl;               // 32..63
    const int bnd = tl << 5;

    const float2 xyl = locv[(tl << 5) + lane];
    const float2 xyh = locv[(th << 5) + lane];
    const unsigned long long xl2 = pack2(xyl.x), yl2 = pack2(xyl.y);
    const unsigned long long xh2 = pack2(xyh.x), yh2 = pack2(xyh.y);

    const ulonglong2* A2 = (const ulonglong2*)sA;
    const ulonglong2* X2 = (const ulonglong2*)sxs;
    const ulonglong2* Y2 = (const ulonglong2*)sys;

    const int lo = c * 504;
    const int hi = lo + 504;

    float suml = 0.0f, sumh = 0.0f;
    {
        const int e1 = (hi < bnd) ? hi : bnd;     // tl segment [lo, e1)
        if (lo < e1) suml = dense_sum_p(A2, X2, Y2, lo, e1, xl2, yl2);
        const int a2 = (lo > bnd) ? lo : bnd;     // th segment [a2, hi)
        if (a2 < hi) sumh = dense_sum_p(A2, X2, Y2, a2 - bnd, hi - bnd, xh2, yh2);
    }

    // Tails: warps 0..3 -> tile tl; warps 4..7 -> tile th (scalar reads).
    if (wid < 4) {
        const int base = tl << 5;
#pragma unroll
        for (int jt = 0; jt < 31; jt++) {
            float u = fmaf(xyl.x, sxs[base + jt],
                      fmaf(xyl.y, sys[base + jt], sA[base + jt]));
            float e = ex2f(u);
            suml += (jt < lane) ? e : 0.0f;
        }
    } else if (wid < 8) {
        const int base = th << 5;
#pragma unroll
        for (int jt = 0; jt < 31; jt++) {
            float u = fmaf(xyh.x, sxs[base + jt],
                      fmaf(xyh.y, sys[base + jt], sA[base + jt]));
            float e = ex2f(u);
            sumh += (jt < lane) ? e : 0.0f;
        }
    }

    saccl[wid][lane] = suml;
    sacch[wid][lane] = sumh;
    __syncthreads();

    // ---- Phase 3: reduction + epilogue (warps 0..7) ----
    if (wid < 8) {
        const bool low = (wid < 4);
        const int  ss  = wid & 3;
        const int  t_o = low ? (k + (ss << 3)) : (63 - (k + (ss << 3)));
        const int  i   = (t_o << 5) + lane;
        const float2 xyo = locv[(t_o << 5) + lane];

        float S = 0.0f;
#pragma unroll
        for (int m = 0; m < 4; m++)
            S += low ? saccl[ss + (m << 2)][lane] : sacch[ss + (m << 2)][lane];

        float res;
        if (i == 0) {
            const float mu0 = *mu0_p;
            const float ls0 = *ls0_p;
            const float iv  = __expf(-2.0f * ls0);
            const float dx = xyo.x - mu0, dy = xyo.y - mu0;
            res = -0.5f * iv * fmaf(dx, dx, dy * dy) - 2.0f * ls0 - LOG2PI_F;
        } else {
            const float B2 = -h2l * fmaf(xyo.x, xyo.x, xyo.y * xyo.y);
            const float K  = 2.0f * sls + LOG2PI_F;
            res = __logf(S) + LN2F * B2 - K - __logf(sE[i]);
        }
        out[n * TT + i] = res;
    }
}

// ---------------------------------------------------------------------------
extern "C" void kernel_launch(void* const* d_in, const int* in_sizes, int n_in,
                              void* d_out, int out_size) {
    const float* tim  = (const float*)d_in[0];  // (N, T, 1)
    const float* loc  = (const float*)d_in[1];  // (N, T, 2)
    const float* mu0  = (const float*)d_in[2];
    const float* ls0  = (const float*)d_in[3];
    const float* cd   = (const float*)d_in[4];
    const float* sls  = (const float*)d_in[5];
    float* out = (float*)d_out;

    const int N = in_sizes[0] / TT;             // 16

    fused_kernel<<<N * 8, 512>>>(tim, loc, mu0, ls0, cd, sls, out);
}